// round 16
// baseline (speedup 1.0000x reference)
#include <cuda_runtime.h>
#include <cuda_fp16.h>
#include <cstdint>

#define HIDDEN   128
#define NGRAPH   512
#define NCLS     10
#define LAYERS   3
#define MAXN     100000
#define MAXE     1600000
#define NH       (12800000)   /* MAXN * HIDDEN */

// ---------------- scratch (device globals: no allocation allowed) ----------
__device__ float  g_tmp[NH];
__device__ float  g_zA [NH];
__device__ float  g_zB [NH];
__device__ __half g_xh [NH];
__device__ __half g_zhA[NH];
__device__ __half g_zhB[NH];
__device__ float  g_pool[NGRAPH * LAYERS * HIDDEN];
__device__ float  g_cnt [NGRAPH];
__device__ float  g_stats[LAYERS * 2 * HIDDEN];
__device__ float  g_aff  [LAYERS * 2 * HIDDEN];
// CSR scratch
__device__ int g_deg   [MAXN + 1];
__device__ int g_rowptr[MAXN + 1];
__device__ int g_cursor[MAXN];
__device__ int g_csr   [MAXE];
__device__ int g_bsum  [256];

// sizes for the fused kernel's dynamic smem
#define AS_FLOATS   (32 * 136)
#define BS_FLOATS   (32 * 128)
#define AGG_FLOATS  (128 * 132)
#define SMEM_FUSED  ((AS_FLOATS + BS_FLOATS + AGG_FLOATS) * 4)

// ---------------- helpers ---------------------------------------------------
__device__ __forceinline__ void red_add_v4(float* addr, float a, float b, float c, float d) {
    asm volatile("red.global.add.v4.f32 [%0], {%1, %2, %3, %4};"
                 :: "l"(addr), "f"(a), "f"(b), "f"(c), "f"(d) : "memory");
}

// ---------------- per-graph node counts -------------------------------------
__global__ void count_kernel(const int* __restrict__ batch, float* __restrict__ cnt, int N) {
    int i = blockIdx.x * blockDim.x + threadIdx.x;
    if (i < N) atomicAdd(&cnt[batch[i]], 1.0f);
}

// ---------------- fp32 -> fp16 copy ------------------------------------------
__global__ void f2h_kernel(const float* __restrict__ in, __half* __restrict__ out, int n4) {
    int i = blockIdx.x * blockDim.x + threadIdx.x;
    if (i < n4) {
        float4 v = ((const float4*)in)[i];
        __half2 h0 = __floats2half2_rn(v.x, v.y);
        __half2 h1 = __floats2half2_rn(v.z, v.w);
        ((__half2*)out)[2 * i]     = h0;
        ((__half2*)out)[2 * i + 1] = h1;
    }
}

// ---------------- CSR build --------------------------------------------------
__global__ void deg_kernel(const int* __restrict__ ei, int* __restrict__ deg, int E) {
    int e = blockIdx.x * blockDim.x + threadIdx.x;
    if (e < E) atomicAdd(&deg[ei[E + e]], 1);   // dst
}

__global__ void scan1_kernel(const int* __restrict__ in, int* __restrict__ out,
                             int* __restrict__ bsum, int M) {
    int gid = blockIdx.x * 1024 + threadIdx.x;
    int v = (gid < M) ? in[gid] : 0;
    int lane = threadIdx.x & 31, wid = threadIdx.x >> 5;
    int x = v;
#pragma unroll
    for (int o = 1; o < 32; o <<= 1) {
        int y = __shfl_up_sync(0xffffffffu, x, o);
        if (lane >= o) x += y;
    }
    __shared__ int ws[32];
    if (lane == 31) ws[wid] = x;
    __syncthreads();
    if (wid == 0) {
        int y = ws[lane];
#pragma unroll
        for (int o = 1; o < 32; o <<= 1) {
            int z = __shfl_up_sync(0xffffffffu, y, o);
            if (lane >= o) y += z;
        }
        ws[lane] = y;
    }
    __syncthreads();
    int excl = x - v + (wid > 0 ? ws[wid - 1] : 0);
    if (gid < M) out[gid] = excl;
    if (threadIdx.x == 0) bsum[blockIdx.x] = ws[31];
}

// parallel exclusive scan over <=256 block sums
__global__ void scan2_kernel(int* __restrict__ bsum, int nb) {
    __shared__ int sh[256];
    int t = threadIdx.x;
    int v = (t < nb) ? bsum[t] : 0;
    sh[t] = v;
    __syncthreads();
#pragma unroll
    for (int o = 1; o < 256; o <<= 1) {
        int x = (t >= o) ? sh[t - o] : 0;
        __syncthreads();
        sh[t] += x;
        __syncthreads();
    }
    if (t < nb) bsum[t] = sh[t] - v;
}

__global__ void scan3_kernel(int* __restrict__ out, const int* __restrict__ bsum, int M) {
    int gid = blockIdx.x * 1024 + threadIdx.x;
    if (gid < M) out[gid] += bsum[blockIdx.x];
}

__global__ void fill_kernel(const int* __restrict__ ei, int* __restrict__ cursor,
                            int* __restrict__ csr, int E) {
    int e = blockIdx.x * blockDim.x + threadIdx.x;
    if (e < E) {
        int d = ei[E + e];
        int slot = atomicAdd(&cursor[d], 1);
        csr[slot] = ei[e];   // src
    }
}

// ---------------- BN affine from stats ---------------------------------------
__global__ void affine_kernel(const float* __restrict__ stats,
                              const float* __restrict__ gamma, const float* __restrict__ beta,
                              float* __restrict__ aff, int N) {
    int c = threadIdx.x;
    float invN = 1.0f / (float)N;
    float mean = stats[c] * invN;
    float var  = stats[HIDDEN + c] * invN - mean * mean;
    float s = gamma[c] * rsqrtf(var + 1e-5f);
    aff[c]          = s;
    aff[HIDDEN + c] = beta[c] - mean * s;
}

// ================= fused GIN GEMM1 ============================================
// Per CTA: gather neighbor sums (fp16 features) into smem AggS, then
// C = relu( [ s⊙(alpha*A + AggS) + (alpha+deg)*t ] @ W + bias ).
__global__ __launch_bounds__(256, 2)
void gin_gemm1_kernel(const float* __restrict__ A, const __half* __restrict__ hh,
                      const int* __restrict__ rowptr, const int* __restrict__ csr,
                      const float* __restrict__ epsp, const int* __restrict__ deg,
                      const float* __restrict__ aff,
                      const float* __restrict__ W, const float* __restrict__ bias,
                      float* __restrict__ C, int N) {
    extern __shared__ char sbuf[];
    float (*As)[136] = (float(*)[136])sbuf;
    float (*Bs)[128] = (float(*)[128])(sbuf + AS_FLOATS * 4);
    float* AggS      = (float*)(sbuf + (AS_FLOATS + BS_FLOATS) * 4);
    __shared__ float aff_s[HIDDEN], aff_t[HIDDEN];

    const int tid = threadIdx.x;
    const int warp = tid >> 5, lane = tid & 31;
    const int tx = tid & 15;
    const int ty = tid >> 4;
    const int row0 = ty * 8;
    const int col0 = tx * 8;
    const int block_m = blockIdx.x * 128;

    const float alpha = 1.0f + __ldg(epsp);
    const bool has_aff = (aff != nullptr);
    if (has_aff && tid < HIDDEN) {
        aff_s[tid] = aff[tid];
        aff_t[tid] = aff[HIDDEN + tid];
    }

    // ---- gather phase: AggS[r][c] = sum of fp16 neighbor features -----------
    for (int r = warp; r < 128; r += 8) {
        int gm = block_m + r;
        float a0 = 0.f, a1 = 0.f, a2 = 0.f, a3 = 0.f;
        if (gm < N) {
            int s = __ldg(&rowptr[gm]), e = __ldg(&rowptr[gm + 1]);
            int i = s;
            for (; i + 2 <= e; i += 2) {
                int s0 = __ldg(&csr[i]);
                int s1 = __ldg(&csr[i + 1]);
                uint2 v0 = __ldg((const uint2*)(hh + (size_t)s0 * HIDDEN) + lane);
                uint2 v1 = __ldg((const uint2*)(hh + (size_t)s1 * HIDDEN) + lane);
                float2 f;
                f = __half22float2(*(__half2*)&v0.x); a0 += f.x; a1 += f.y;
                f = __half22float2(*(__half2*)&v0.y); a2 += f.x; a3 += f.y;
                f = __half22float2(*(__half2*)&v1.x); a0 += f.x; a1 += f.y;
                f = __half22float2(*(__half2*)&v1.y); a2 += f.x; a3 += f.y;
            }
            if (i < e) {
                int s0 = __ldg(&csr[i]);
                uint2 v0 = __ldg((const uint2*)(hh + (size_t)s0 * HIDDEN) + lane);
                float2 f;
                f = __half22float2(*(__half2*)&v0.x); a0 += f.x; a1 += f.y;
                f = __half22float2(*(__half2*)&v0.y); a2 += f.x; a3 += f.y;
            }
        }
        *(float4*)&AggS[r * 132 + lane * 4] = make_float4(a0, a1, a2, a3);
    }
    __syncthreads();

    // ---- mainloop ------------------------------------------------------------
    unsigned long long acc[4][8];
#pragma unroll
    for (int i = 0; i < 4; i++)
#pragma unroll
        for (int j = 0; j < 8; j++) acc[i][j] = 0ull;

    for (int kk = 0; kk < HIDDEN; kk += 32) {
#pragma unroll
        for (int it = 0; it < 4; it++) {
            int flat = tid + it * 256;
            int m    = flat >> 3;
            int k4   = (flat & 7) * 4;
            int gm   = block_m + m;
            float4 v = make_float4(0.f, 0.f, 0.f, 0.f);
            if (gm < N) {
                float4 z = *(const float4*)(A + (size_t)gm * HIDDEN + kk + k4);
                float4 u = *(const float4*)&AggS[m * 132 + kk + k4];
                v.x = fmaf(alpha, z.x, u.x);
                v.y = fmaf(alpha, z.y, u.y);
                v.z = fmaf(alpha, z.z, u.z);
                v.w = fmaf(alpha, z.w, u.w);
                if (has_aff) {
                    float coef = alpha + (float)__ldg(&deg[gm]);
                    int c = kk + k4;
                    v.x = fmaf(aff_s[c + 0], v.x, coef * aff_t[c + 0]);
                    v.y = fmaf(aff_s[c + 1], v.y, coef * aff_t[c + 1]);
                    v.z = fmaf(aff_s[c + 2], v.z, coef * aff_t[c + 2]);
                    v.w = fmaf(aff_s[c + 3], v.w, coef * aff_t[c + 3]);
                }
            }
            As[k4 + 0][m] = v.x;
            As[k4 + 1][m] = v.y;
            As[k4 + 2][m] = v.z;
            As[k4 + 3][m] = v.w;
        }
#pragma unroll
        for (int it = 0; it < 4; it++) {
            int flat = tid + it * 256;
            int k    = flat >> 5;
            int n4   = (flat & 31) * 4;
            *(float4*)&Bs[k][n4] = *(const float4*)(W + (size_t)(kk + k) * HIDDEN + n4);
        }
        __syncthreads();

#pragma unroll 8
        for (int k = 0; k < 32; k++) {
            ulonglong2 A0 = *(const ulonglong2*)&As[k][row0];
            ulonglong2 A1 = *(const ulonglong2*)&As[k][row0 + 4];
            unsigned long long ap[4] = {A0.x, A0.y, A1.x, A1.y};
            float4 b0 = *(const float4*)&Bs[k][col0];
            float4 b1 = *(const float4*)&Bs[k][col0 + 4];
            float bb[8] = {b0.x, b0.y, b0.z, b0.w, b1.x, b1.y, b1.z, b1.w};
            unsigned long long bd[8];
#pragma unroll
            for (int j = 0; j < 8; j++)
                asm("mov.b64 %0, {%1, %1};" : "=l"(bd[j]) : "f"(bb[j]));
#pragma unroll
            for (int i2 = 0; i2 < 4; i2++)
#pragma unroll
                for (int j = 0; j < 8; j++)
                    asm("fma.rn.f32x2 %0, %1, %2, %0;"
                        : "+l"(acc[i2][j]) : "l"(ap[i2]), "l"(bd[j]));
        }
        __syncthreads();
    }

    float o[8][8];
#pragma unroll
    for (int i2 = 0; i2 < 4; i2++)
#pragma unroll
        for (int j = 0; j < 8; j++)
            asm("mov.b64 {%0, %1}, %2;"
                : "=f"(o[2 * i2][j]), "=f"(o[2 * i2 + 1][j]) : "l"(acc[i2][j]));

    float bv[8];
#pragma unroll
    for (int j = 0; j < 8; j++) bv[j] = bias[col0 + j];

#pragma unroll
    for (int i = 0; i < 8; i++) {
        int gm = block_m + row0 + i;
        if (gm < N) {
#pragma unroll
            for (int j = 0; j < 8; j++) o[i][j] = fmaxf(o[i][j] + bv[j], 0.f);
            *(float4*)(C + (size_t)gm * HIDDEN + col0)     = *(float4*)&o[i][0];
            *(float4*)(C + (size_t)gm * HIDDEN + col0 + 4) = *(float4*)&o[i][4];
        }
    }
}

// ================= GEMM2: relu(A@W2+b2), stats + pool + fp16-copy epilogue ===
__global__ __launch_bounds__(256, 2)
void gemm2_kernel(const float* __restrict__ A,
                  const float* __restrict__ W, const float* __restrict__ bias,
                  float* __restrict__ C, __half* __restrict__ Ch, int N,
                  float* __restrict__ stats, float* __restrict__ pool,
                  const int* __restrict__ batch, int loff) {
    __shared__ __align__(16) float As[32][HIDDEN + 8];
    __shared__ __align__(16) float Bs[32][HIDDEN];

    const int tid = threadIdx.x;
    const int tx = tid & 15;
    const int ty = tid >> 4;
    const int row0 = ty * 8;
    const int col0 = tx * 8;
    const int block_m = blockIdx.x * 128;

    unsigned long long acc[4][8];
#pragma unroll
    for (int i = 0; i < 4; i++)
#pragma unroll
        for (int j = 0; j < 8; j++) acc[i][j] = 0ull;

    for (int kk = 0; kk < HIDDEN; kk += 32) {
#pragma unroll
        for (int it = 0; it < 4; it++) {
            int flat = tid + it * 256;
            int m    = flat >> 3;
            int k4   = (flat & 7) * 4;
            int gm   = block_m + m;
            float4 v = make_float4(0.f, 0.f, 0.f, 0.f);
            if (gm < N) v = *(const float4*)(A + (size_t)gm * HIDDEN + kk + k4);
            As[k4 + 0][m] = v.x;
            As[k4 + 1][m] = v.y;
            As[k4 + 2][m] = v.z;
            As[k4 + 3][m] = v.w;
        }
#pragma unroll
        for (int it = 0; it < 4; it++) {
            int flat = tid + it * 256;
            int k    = flat >> 5;
            int n4   = (flat & 31) * 4;
            *(float4*)&Bs[k][n4] = *(const float4*)(W + (size_t)(kk + k) * HIDDEN + n4);
        }
        __syncthreads();

#pragma unroll 8
        for (int k = 0; k < 32; k++) {
            ulonglong2 A0 = *(const ulonglong2*)&As[k][row0];
            ulonglong2 A1 = *(const ulonglong2*)&As[k][row0 + 4];
            unsigned long long ap[4] = {A0.x, A0.y, A1.x, A1.y};
            float4 b0 = *(const float4*)&Bs[k][col0];
            float4 b1 = *(const float4*)&Bs[k][col0 + 4];
            float bb[8] = {b0.x, b0.y, b0.z, b0.w, b1.x, b1.y, b1.z, b1.w};
            unsigned long long bd[8];
#pragma unroll
            for (int j = 0; j < 8; j++)
                asm("mov.b64 %0, {%1, %1};" : "=l"(bd[j]) : "f"(bb[j]));
#pragma unroll
            for (int i2 = 0; i2 < 4; i2++)
#pragma unroll
                for (int j = 0; j < 8; j++)
                    asm("fma.rn.f32x2 %0, %1, %2, %0;"
                        : "+l"(acc[i2][j]) : "l"(ap[i2]), "l"(bd[j]));
        }
        __syncthreads();
    }

    float o[8][8];
#pragma unroll
    for (int i2 = 0; i2 < 4; i2++)
#pragma unroll
        for (int j = 0; j < 8; j++)
            asm("mov.b64 {%0, %1}, %2;"
                : "=f"(o[2 * i2][j]), "=f"(o[2 * i2 + 1][j]) : "l"(acc[i2][j]));

    float bv[8];
#pragma unroll
    for (int j = 0; j < 8; j++) bv[j] = bias[col0 + j];

#pragma unroll
    for (int i = 0; i < 8; i++) {
#pragma unroll
        for (int j = 0; j < 8; j++) o[i][j] = fmaxf(o[i][j] + bv[j], 0.f);
        int gm = block_m + row0 + i;
        if (gm < N) {
            *(float4*)(C + (size_t)gm * HIDDEN + col0)     = *(float4*)&o[i][0];
            *(float4*)(C + (size_t)gm * HIDDEN + col0 + 4) = *(float4*)&o[i][4];
            // fp16 copy for next layer's gather
            __half2 h[4];
            h[0] = __floats2half2_rn(o[i][0], o[i][1]);
            h[1] = __floats2half2_rn(o[i][2], o[i][3]);
            h[2] = __floats2half2_rn(o[i][4], o[i][5]);
            h[3] = __floats2half2_rn(o[i][6], o[i][7]);
            *(uint2*)(Ch + (size_t)gm * HIDDEN + col0)     = *(uint2*)&h[0];
            *(uint2*)(Ch + (size_t)gm * HIDDEN + col0 + 4) = *(uint2*)&h[2];
            int b = __ldg(&batch[gm]);
            float* p = pool + (size_t)b * (LAYERS * HIDDEN) + loff + col0;
            red_add_v4(p,     o[i][0], o[i][1], o[i][2], o[i][3]);
            red_add_v4(p + 4, o[i][4], o[i][5], o[i][6], o[i][7]);
        }
    }

    // column sum/sumsq reduction into stats
    float psum[8], psq[8];
#pragma unroll
    for (int j = 0; j < 8; j++) { psum[j] = 0.f; psq[j] = 0.f; }
#pragma unroll
    for (int i = 0; i < 8; i++) {
        int gm = block_m + row0 + i;
        if (gm < N) {
#pragma unroll
            for (int j = 0; j < 8; j++) {
                psum[j] += o[i][j];
                psq[j]  += o[i][j] * o[i][j];
            }
        }
    }
    float* red = &As[0][0];
#pragma unroll
    for (int j = 0; j < 8; j += 4) {
        *(float4*)&red[ty * 128 + col0 + j]        = *(float4*)&psum[j];
        *(float4*)&red[2048 + ty * 128 + col0 + j] = *(float4*)&psq[j];
    }
    __syncthreads();
    if (tid < HIDDEN) {
        float s = 0.f, q = 0.f;
#pragma unroll
        for (int t = 0; t < 16; t++) {
            s += red[t * 128 + tid];
            q += red[2048 + t * 128 + tid];
        }
        atomicAdd(&stats[tid], s);
        atomicAdd(&stats[HIDDEN + tid], q);
    }
}

// ---------------- readout head (applies BN affine to raw pools) --------------
__global__ void head_kernel(const float* __restrict__ pool, const float* __restrict__ cnt,
                            const float* __restrict__ aff,
                            const float* __restrict__ l1w, const float* __restrict__ l1b,
                            const float* __restrict__ l2w, const float* __restrict__ l2b,
                            float* __restrict__ out) {
    __shared__ float grow[LAYERS * HIDDEN];
    __shared__ float o1[HIDDEN];
    int g = blockIdx.x, t = threadIdx.x;
    float c0 = cnt[g];
    float inv = 1.0f / fmaxf(c0, 1.0f);
    for (int j = t; j < LAYERS * HIDDEN; j += HIDDEN) {
        int l = j >> 7, c = j & 127;
        float raw = pool[(size_t)g * (LAYERS * HIDDEN) + j];
        float s = aff[l * 2 * HIDDEN + c];
        float tt = aff[l * 2 * HIDDEN + HIDDEN + c];
        grow[j] = (s * raw + c0 * tt) * inv;
    }
    __syncthreads();

    float acc = l1b[t];
    for (int j = 0; j < LAYERS * HIDDEN; j++)
        acc = fmaf(grow[j], l1w[(size_t)j * HIDDEN + t], acc);
    o1[t] = fmaxf(acc, 0.f);
    __syncthreads();

    if (t < NCLS) {
        float a = l2b[t];
        for (int c2 = 0; c2 < HIDDEN; c2++)
            a = fmaf(o1[c2], l2w[(size_t)c2 * NCLS + t], a);
        out[(size_t)g * NCLS + t] = a;
    }
}

// ---------------- launcher ----------------------------------------------------
extern "C" void kernel_launch(void* const* d_in, const int* in_sizes, int n_in,
                              void* d_out, int out_size) {
    const float* x     = (const float*)d_in[0];
    const int*   ei    = (const int*)  d_in[1];
    const int*   batch = (const int*)  d_in[2];
    const float* W1    = (const float*)d_in[3];
    const float* b1    = (const float*)d_in[4];
    const float* W2    = (const float*)d_in[5];
    const float* b2    = (const float*)d_in[6];
    const float* gamma = (const float*)d_in[7];
    const float* beta  = (const float*)d_in[8];
    const float* epsg  = (const float*)d_in[9];
    const float* l1w   = (const float*)d_in[10];
    const float* l1b   = (const float*)d_in[11];
    const float* l2w   = (const float*)d_in[12];
    const float* l2b   = (const float*)d_in[13];
    float* out = (float*)d_out;

    const int N = in_sizes[0] / HIDDEN;
    const int E = in_sizes[1] / 2;
    const int M = N + 1;

    float *tmp, *zA, *zB, *pool, *cnt, *stats, *aff;
    __half *xh, *zhA, *zhB;
    int *deg, *rowptr, *cursor, *csr, *bsum;
    cudaGetSymbolAddress((void**)&tmp,    g_tmp);
    cudaGetSymbolAddress((void**)&zA,     g_zA);
    cudaGetSymbolAddress((void**)&zB,     g_zB);
    cudaGetSymbolAddress((void**)&xh,     g_xh);
    cudaGetSymbolAddress((void**)&zhA,    g_zhA);
    cudaGetSymbolAddress((void**)&zhB,    g_zhB);
    cudaGetSymbolAddress((void**)&pool,   g_pool);
    cudaGetSymbolAddress((void**)&cnt,    g_cnt);
    cudaGetSymbolAddress((void**)&stats,  g_stats);
    cudaGetSymbolAddress((void**)&aff,    g_aff);
    cudaGetSymbolAddress((void**)&deg,    g_deg);
    cudaGetSymbolAddress((void**)&rowptr, g_rowptr);
    cudaGetSymbolAddress((void**)&cursor, g_cursor);
    cudaGetSymbolAddress((void**)&csr,    g_csr);
    cudaGetSymbolAddress((void**)&bsum,   g_bsum);

    cudaFuncSetAttribute(gin_gemm1_kernel,
                         cudaFuncAttributeMaxDynamicSharedMemorySize, SMEM_FUSED);

    cudaMemsetAsync(pool,  0, (size_t)NGRAPH * LAYERS * HIDDEN * sizeof(float), 0);
    cudaMemsetAsync(cnt,   0, (size_t)NGRAPH * sizeof(float), 0);
    cudaMemsetAsync(stats, 0, (size_t)LAYERS * 2 * HIDDEN * sizeof(float), 0);
    count_kernel<<<(N + 255) / 256, 256>>>(batch, cnt, N);

    // fp16 copy of x (for layer-0 gather)
    const int n4 = N * 32;
    f2h_kernel<<<(n4 + 255) / 256, 256>>>(x, xh, n4);

    // ---- CSR build (once) ----
    const int nb = (M + 1023) / 1024;
    cudaMemsetAsync(deg, 0, (size_t)M * sizeof(int), 0);
    deg_kernel<<<(E + 255) / 256, 256>>>(ei, deg, E);
    scan1_kernel<<<nb, 1024>>>(deg, rowptr, bsum, M);
    scan2_kernel<<<1, 256>>>(bsum, nb);
    scan3_kernel<<<nb, 1024>>>(rowptr, bsum, M);
    cudaMemcpyAsync(cursor, rowptr, (size_t)N * sizeof(int), cudaMemcpyDeviceToDevice, 0);
    fill_kernel<<<(E + 255) / 256, 256>>>(ei, cursor, csr, E);

    const int gemm_grid = (N + 127) / 128;

    const float*  zin  = x;
    const __half* zhin = xh;
    float*  zouts [LAYERS] = {zA,  zB,  zA};
    __half* zhouts[LAYERS] = {zhA, zhB, zhA};

    for (int l = 0; l < LAYERS; l++) {
        const float* aff_prev = (l == 0) ? nullptr : (aff + (size_t)(l - 1) * 2 * HIDDEN);

        gin_gemm1_kernel<<<gemm_grid, 256, SMEM_FUSED>>>(
            zin, zhin, rowptr, csr, epsg + l, deg, aff_prev,
            W1 + (size_t)l * HIDDEN * HIDDEN, b1 + (size_t)l * HIDDEN,
            tmp, N);

        gemm2_kernel<<<gemm_grid, 256>>>(
            tmp, W2 + (size_t)l * HIDDEN * HIDDEN, b2 + (size_t)l * HIDDEN,
            zouts[l], zhouts[l], N,
            stats + (size_t)l * 2 * HIDDEN, pool, batch, l * HIDDEN);

        affine_kernel<<<1, HIDDEN>>>(stats + (size_t)l * 2 * HIDDEN,
                                     gamma + (size_t)l * HIDDEN,
                                     beta  + (size_t)l * HIDDEN,
                                     aff + (size_t)l * 2 * HIDDEN, N);
        zin  = zouts[l];
        zhin = zhouts[l];
    }

    head_kernel<<<NGRAPH, HIDDEN>>>(pool, cnt, aff, l1w, l1b, l2w, l2b, out);
}

// round 17
// speedup vs baseline: 1.1046x; 1.1046x over previous
#include <cuda_runtime.h>
#include <cstdint>

#define HIDDEN   128
#define NGRAPH   512
#define NCLS     10
#define LAYERS   3
#define MAXN     100000
#define MAXE     1600000
#define NH       (12800000)   /* MAXN * HIDDEN */

// ---------------- scratch (device globals: no allocation allowed) ----------
__device__ float g_agg[NH];
__device__ float g_zA [NH];
__device__ float g_zB [NH];
__device__ float g_pool[NGRAPH * LAYERS * HIDDEN];
__device__ float g_cnt [NGRAPH];
__device__ float g_stats[LAYERS * 2 * HIDDEN];
__device__ float g_aff  [LAYERS * 2 * HIDDEN];
// CSR scratch
__device__ int g_deg   [MAXN + 1];
__device__ int g_rowptr[MAXN + 1];
__device__ int g_cursor[MAXN];
__device__ int g_csr   [MAXE];
__device__ int g_bsum  [256];

// fused kernel dynamic smem layout (floats)
#define AS_FLOATS   (32 * 136)
#define BS_FLOATS   (32 * 128)
#define C1_FLOATS   (128 * 132)
#define SMEM_FUSED  ((AS_FLOATS + BS_FLOATS + C1_FLOATS) * 4)

// ---------------- helpers ---------------------------------------------------
__device__ __forceinline__ void red_add_v4(float* addr, float a, float b, float c, float d) {
    asm volatile("red.global.add.v4.f32 [%0], {%1, %2, %3, %4};"
                 :: "l"(addr), "f"(a), "f"(b), "f"(c), "f"(d) : "memory");
}

// ---------------- per-graph node counts -------------------------------------
__global__ void count_kernel(const int* __restrict__ batch, float* __restrict__ cnt, int N) {
    int i = blockIdx.x * blockDim.x + threadIdx.x;
    if (i < N) atomicAdd(&cnt[batch[i]], 1.0f);
}

// ---------------- CSR build --------------------------------------------------
__global__ void deg_kernel(const int* __restrict__ ei, int* __restrict__ deg, int E) {
    int e = blockIdx.x * blockDim.x + threadIdx.x;
    if (e < E) atomicAdd(&deg[ei[E + e]], 1);   // dst
}

__global__ void scan1_kernel(const int* __restrict__ in, int* __restrict__ out,
                             int* __restrict__ bsum, int M) {
    int gid = blockIdx.x * 1024 + threadIdx.x;
    int v = (gid < M) ? in[gid] : 0;
    int lane = threadIdx.x & 31, wid = threadIdx.x >> 5;
    int x = v;
#pragma unroll
    for (int o = 1; o < 32; o <<= 1) {
        int y = __shfl_up_sync(0xffffffffu, x, o);
        if (lane >= o) x += y;
    }
    __shared__ int ws[32];
    if (lane == 31) ws[wid] = x;
    __syncthreads();
    if (wid == 0) {
        int y = ws[lane];
#pragma unroll
        for (int o = 1; o < 32; o <<= 1) {
            int z = __shfl_up_sync(0xffffffffu, y, o);
            if (lane >= o) y += z;
        }
        ws[lane] = y;
    }
    __syncthreads();
    int excl = x - v + (wid > 0 ? ws[wid - 1] : 0);
    if (gid < M) out[gid] = excl;
    if (threadIdx.x == 0) bsum[blockIdx.x] = ws[31];
}

__global__ void scan2_kernel(int* __restrict__ bsum, int nb) {
    __shared__ int sh[256];
    int t = threadIdx.x;
    int v = (t < nb) ? bsum[t] : 0;
    sh[t] = v;
    __syncthreads();
#pragma unroll
    for (int o = 1; o < 256; o <<= 1) {
        int x = (t >= o) ? sh[t - o] : 0;
        __syncthreads();
        sh[t] += x;
        __syncthreads();
    }
    if (t < nb) bsum[t] = sh[t] - v;
}

__global__ void scan3_kernel(int* __restrict__ out, const int* __restrict__ bsum, int M) {
    int gid = blockIdx.x * 1024 + threadIdx.x;
    if (gid < M) out[gid] += bsum[blockIdx.x];
}

__global__ void fill_kernel(const int* __restrict__ ei, int* __restrict__ cursor,
                            int* __restrict__ csr, int E) {
    int e = blockIdx.x * blockDim.x + threadIdx.x;
    if (e < E) {
        int d = ei[E + e];
        int slot = atomicAdd(&cursor[d], 1);
        csr[slot] = ei[e];   // src
    }
}

// ---------------- CSR gather-aggregate (fp32, 4-edge unroll) ------------------
__global__ void agg_csr_kernel(const float* __restrict__ h, const int* __restrict__ rowptr,
                               const int* __restrict__ csr, float* __restrict__ agg, int N) {
    int t = blockIdx.x * blockDim.x + threadIdx.x;
    int node = t >> 5;
    if (node >= N) return;
    int lane = t & 31;
    int s = rowptr[node], e = rowptr[node + 1];
    float4 a0 = make_float4(0.f, 0.f, 0.f, 0.f);
    float4 a1 = make_float4(0.f, 0.f, 0.f, 0.f);
    float4 a2 = make_float4(0.f, 0.f, 0.f, 0.f);
    float4 a3 = make_float4(0.f, 0.f, 0.f, 0.f);
    int i = s;
    for (; i + 4 <= e; i += 4) {
        int s0 = __ldg(&csr[i]);
        int s1 = __ldg(&csr[i + 1]);
        int s2 = __ldg(&csr[i + 2]);
        int s3 = __ldg(&csr[i + 3]);
        float4 v0 = ((const float4*)h)[(size_t)s0 * 32 + lane];
        float4 v1 = ((const float4*)h)[(size_t)s1 * 32 + lane];
        float4 v2 = ((const float4*)h)[(size_t)s2 * 32 + lane];
        float4 v3 = ((const float4*)h)[(size_t)s3 * 32 + lane];
        a0.x += v0.x; a0.y += v0.y; a0.z += v0.z; a0.w += v0.w;
        a1.x += v1.x; a1.y += v1.y; a1.z += v1.z; a1.w += v1.w;
        a2.x += v2.x; a2.y += v2.y; a2.z += v2.z; a2.w += v2.w;
        a3.x += v3.x; a3.y += v3.y; a3.z += v3.z; a3.w += v3.w;
    }
    for (; i < e; i++) {
        int s0 = __ldg(&csr[i]);
        float4 v0 = ((const float4*)h)[(size_t)s0 * 32 + lane];
        a0.x += v0.x; a0.y += v0.y; a0.z += v0.z; a0.w += v0.w;
    }
    a0.x += a1.x; a0.y += a1.y; a0.z += a1.z; a0.w += a1.w;
    a2.x += a3.x; a2.y += a3.y; a2.z += a3.z; a2.w += a3.w;
    a0.x += a2.x; a0.y += a2.y; a0.z += a2.z; a0.w += a2.w;
    ((float4*)agg)[(size_t)node * 32 + lane] = a0;
}

// ---------------- BN affine from stats ---------------------------------------
__global__ void affine_kernel(const float* __restrict__ stats,
                              const float* __restrict__ gamma, const float* __restrict__ beta,
                              float* __restrict__ aff, int N) {
    int c = threadIdx.x;
    float invN = 1.0f / (float)N;
    float mean = stats[c] * invN;
    float var  = stats[HIDDEN + c] * invN - mean * mean;
    float s = gamma[c] * rsqrtf(var + 1e-5f);
    aff[c]          = s;
    aff[HIDDEN + c] = beta[c] - mean * s;
}

// ================= fused GIN MLP: both GEMMs in one kernel ====================
// Aeff = s⊙(alpha*A + Agg) + (alpha+deg)*t    (aff==null -> identity affine)
// t1   = relu(Aeff @ W1 + b1)                 (parked in smem C1s)
// C    = relu(t1 @ W2 + b2)
// epilogue: per-graph pool red_add + column sum/sumsq into stats.
__global__ __launch_bounds__(256, 2)
void gin_mlp_kernel(const float* __restrict__ A, const float* __restrict__ Agg,
                    const float* __restrict__ epsp, const int* __restrict__ deg,
                    const float* __restrict__ aff,
                    const float* __restrict__ W1, const float* __restrict__ b1,
                    const float* __restrict__ W2, const float* __restrict__ b2,
                    float* __restrict__ C, int N,
                    float* __restrict__ stats, float* __restrict__ pool,
                    const int* __restrict__ batch, int loff) {
    extern __shared__ char sbuf[];
    float (*As)[136]  = (float(*)[136])sbuf;
    float (*Bs)[128]  = (float(*)[128])(sbuf + AS_FLOATS * 4);
    float (*C1s)[132] = (float(*)[132])(sbuf + (AS_FLOATS + BS_FLOATS) * 4);
    __shared__ float aff_s[HIDDEN], aff_t[HIDDEN];

    const int tid = threadIdx.x;
    const int tx = tid & 15;
    const int ty = tid >> 4;
    const int row0 = ty * 8;
    const int col0 = tx * 8;
    const int block_m = blockIdx.x * 128;

    const float alpha = 1.0f + __ldg(epsp);
    const bool has_aff = (aff != nullptr);
    if (has_aff && tid < HIDDEN) {
        aff_s[tid] = aff[tid];
        aff_t[tid] = aff[HIDDEN + tid];
    }
    if (has_aff) __syncthreads();

    unsigned long long acc[4][8];
#pragma unroll
    for (int i = 0; i < 4; i++)
#pragma unroll
        for (int j = 0; j < 8; j++) acc[i][j] = 0ull;

    // =================== phase 1: Aeff @ W1 ===================
    for (int kk = 0; kk < HIDDEN; kk += 32) {
#pragma unroll
        for (int it = 0; it < 4; it++) {
            int flat = tid + it * 256;
            int m    = flat >> 3;
            int k4   = (flat & 7) * 4;
            int gm   = block_m + m;
            float4 v = make_float4(0.f, 0.f, 0.f, 0.f);
            if (gm < N) {
                float4 z = *(const float4*)(A   + (size_t)gm * HIDDEN + kk + k4);
                float4 u = *(const float4*)(Agg + (size_t)gm * HIDDEN + kk + k4);
                v.x = fmaf(alpha, z.x, u.x);
                v.y = fmaf(alpha, z.y, u.y);
                v.z = fmaf(alpha, z.z, u.z);
                v.w = fmaf(alpha, z.w, u.w);
                if (has_aff) {
                    float coef = alpha + (float)__ldg(&deg[gm]);
                    int c = kk + k4;
                    v.x = fmaf(aff_s[c + 0], v.x, coef * aff_t[c + 0]);
                    v.y = fmaf(aff_s[c + 1], v.y, coef * aff_t[c + 1]);
                    v.z = fmaf(aff_s[c + 2], v.z, coef * aff_t[c + 2]);
                    v.w = fmaf(aff_s[c + 3], v.w, coef * aff_t[c + 3]);
                }
            }
            As[k4 + 0][m] = v.x;
            As[k4 + 1][m] = v.y;
            As[k4 + 2][m] = v.z;
            As[k4 + 3][m] = v.w;
        }
#pragma unroll
        for (int it = 0; it < 4; it++) {
            int flat = tid + it * 256;
            int k    = flat >> 5;
            int n4   = (flat & 31) * 4;
            *(float4*)&Bs[k][n4] = *(const float4*)(W1 + (size_t)(kk + k) * HIDDEN + n4);
        }
        __syncthreads();

#pragma unroll 8
        for (int k = 0; k < 32; k++) {
            ulonglong2 A0 = *(const ulonglong2*)&As[k][row0];
            ulonglong2 A1 = *(const ulonglong2*)&As[k][row0 + 4];
            unsigned long long ap[4] = {A0.x, A0.y, A1.x, A1.y};
            float4 b0 = *(const float4*)&Bs[k][col0];
            float4 b1v = *(const float4*)&Bs[k][col0 + 4];
            float bb[8] = {b0.x, b0.y, b0.z, b0.w, b1v.x, b1v.y, b1v.z, b1v.w};
            unsigned long long bd[8];
#pragma unroll
            for (int j = 0; j < 8; j++)
                asm("mov.b64 %0, {%1, %1};" : "=l"(bd[j]) : "f"(bb[j]));
#pragma unroll
            for (int i2 = 0; i2 < 4; i2++)
#pragma unroll
                for (int j = 0; j < 8; j++)
                    asm("fma.rn.f32x2 %0, %1, %2, %0;"
                        : "+l"(acc[i2][j]) : "l"(ap[i2]), "l"(bd[j]));
        }
        __syncthreads();
    }

    // ---- park t1 = relu(acc + b1) in C1s, reset acc --------------------------
    {
        float bv[8];
#pragma unroll
        for (int j = 0; j < 8; j++) bv[j] = b1[col0 + j];
#pragma unroll
        for (int i2 = 0; i2 < 4; i2++) {
#pragma unroll
            for (int j = 0; j < 8; j++) {
                float lo, hi;
                asm("mov.b64 {%0, %1}, %2;" : "=f"(lo), "=f"(hi) : "l"(acc[i2][j]));
                C1s[row0 + 2 * i2    ][col0 + j] = fmaxf(lo + bv[j], 0.f);
                C1s[row0 + 2 * i2 + 1][col0 + j] = fmaxf(hi + bv[j], 0.f);
                acc[i2][j] = 0ull;
            }
        }
    }
    __syncthreads();

    // =================== phase 2: t1 @ W2 ===================
    for (int kk = 0; kk < HIDDEN; kk += 32) {
#pragma unroll
        for (int it = 0; it < 4; it++) {
            int flat = tid + it * 256;
            int m    = flat >> 3;
            int k4   = (flat & 7) * 4;
            float4 v = *(const float4*)&C1s[m][kk + k4];
            As[k4 + 0][m] = v.x;
            As[k4 + 1][m] = v.y;
            As[k4 + 2][m] = v.z;
            As[k4 + 3][m] = v.w;
        }
#pragma unroll
        for (int it = 0; it < 4; it++) {
            int flat = tid + it * 256;
            int k    = flat >> 5;
            int n4   = (flat & 31) * 4;
            *(float4*)&Bs[k][n4] = *(const float4*)(W2 + (size_t)(kk + k) * HIDDEN + n4);
        }
        __syncthreads();

#pragma unroll 8
        for (int k = 0; k < 32; k++) {
            ulonglong2 A0 = *(const ulonglong2*)&As[k][row0];
            ulonglong2 A1 = *(const ulonglong2*)&As[k][row0 + 4];
            unsigned long long ap[4] = {A0.x, A0.y, A1.x, A1.y};
            float4 b0 = *(const float4*)&Bs[k][col0];
            float4 b1v = *(const float4*)&Bs[k][col0 + 4];
            float bb[8] = {b0.x, b0.y, b0.z, b0.w, b1v.x, b1v.y, b1v.z, b1v.w};
            unsigned long long bd[8];
#pragma unroll
            for (int j = 0; j < 8; j++)
                asm("mov.b64 %0, {%1, %1};" : "=l"(bd[j]) : "f"(bb[j]));
#pragma unroll
            for (int i2 = 0; i2 < 4; i2++)
#pragma unroll
                for (int j = 0; j < 8; j++)
                    asm("fma.rn.f32x2 %0, %1, %2, %0;"
                        : "+l"(acc[i2][j]) : "l"(ap[i2]), "l"(bd[j]));
        }
        __syncthreads();
    }

    // ---- epilogue: relu(acc+b2) -> C, pool, stats ----------------------------
    float o[8][8];
#pragma unroll
    for (int i2 = 0; i2 < 4; i2++)
#pragma unroll
        for (int j = 0; j < 8; j++)
            asm("mov.b64 {%0, %1}, %2;"
                : "=f"(o[2 * i2][j]), "=f"(o[2 * i2 + 1][j]) : "l"(acc[i2][j]));

    float bv[8];
#pragma unroll
    for (int j = 0; j < 8; j++) bv[j] = b2[col0 + j];

#pragma unroll
    for (int i = 0; i < 8; i++) {
#pragma unroll
        for (int j = 0; j < 8; j++) o[i][j] = fmaxf(o[i][j] + bv[j], 0.f);
        int gm = block_m + row0 + i;
        if (gm < N) {
            *(float4*)(C + (size_t)gm * HIDDEN + col0)     = *(float4*)&o[i][0];
            *(float4*)(C + (size_t)gm * HIDDEN + col0 + 4) = *(float4*)&o[i][4];
            int b = __ldg(&batch[gm]);
            float* p = pool + (size_t)b * (LAYERS * HIDDEN) + loff + col0;
            red_add_v4(p,     o[i][0], o[i][1], o[i][2], o[i][3]);
            red_add_v4(p + 4, o[i][4], o[i][5], o[i][6], o[i][7]);
        }
    }

    // column sum/sumsq reduction into stats (reuse As region)
    float psum[8], psq[8];
#pragma unroll
    for (int j = 0; j < 8; j++) { psum[j] = 0.f; psq[j] = 0.f; }
#pragma unroll
    for (int i = 0; i < 8; i++) {
        int gm = block_m + row0 + i;
        if (gm < N) {
#pragma unroll
            for (int j = 0; j < 8; j++) {
                psum[j] += o[i][j];
                psq[j]  += o[i][j] * o[i][j];
            }
        }
    }
    float* red = &As[0][0];
#pragma unroll
    for (int j = 0; j < 8; j += 4) {
        *(float4*)&red[ty * 128 + col0 + j]        = *(float4*)&psum[j];
        *(float4*)&red[2048 + ty * 128 + col0 + j] = *(float4*)&psq[j];
    }
    __syncthreads();
    if (tid < HIDDEN) {
        float s = 0.f, q = 0.f;
#pragma unroll
        for (int t = 0; t < 16; t++) {
            s += red[t * 128 + tid];
            q += red[2048 + t * 128 + tid];
        }
        atomicAdd(&stats[tid], s);
        atomicAdd(&stats[HIDDEN + tid], q);
    }
}

// ---------------- readout head (applies BN affine to raw pools) --------------
__global__ void head_kernel(const float* __restrict__ pool, const float* __restrict__ cnt,
                            const float* __restrict__ aff,
                            const float* __restrict__ l1w, const float* __restrict__ l1b,
                            const float* __restrict__ l2w, const float* __restrict__ l2b,
                            float* __restrict__ out) {
    __shared__ float grow[LAYERS * HIDDEN];
    __shared__ float o1[HIDDEN];
    int g = blockIdx.x, t = threadIdx.x;
    float c0 = cnt[g];
    float inv = 1.0f / fmaxf(c0, 1.0f);
    for (int j = t; j < LAYERS * HIDDEN; j += HIDDEN) {
        int l = j >> 7, c = j & 127;
        float raw = pool[(size_t)g * (LAYERS * HIDDEN) + j];
        float s = aff[l * 2 * HIDDEN + c];
        float tt = aff[l * 2 * HIDDEN + HIDDEN + c];
        grow[j] = (s * raw + c0 * tt) * inv;
    }
    __syncthreads();

    float acc = l1b[t];
    for (int j = 0; j < LAYERS * HIDDEN; j++)
        acc = fmaf(grow[j], l1w[(size_t)j * HIDDEN + t], acc);
    o1[t] = fmaxf(acc, 0.f);
    __syncthreads();

    if (t < NCLS) {
        float a = l2b[t];
        for (int c2 = 0; c2 < HIDDEN; c2++)
            a = fmaf(o1[c2], l2w[(size_t)c2 * NCLS + t], a);
        out[(size_t)g * NCLS + t] = a;
    }
}

// ---------------- launcher ----------------------------------------------------
extern "C" void kernel_launch(void* const* d_in, const int* in_sizes, int n_in,
                              void* d_out, int out_size) {
    const float* x     = (const float*)d_in[0];
    const int*   ei    = (const int*)  d_in[1];
    const int*   batch = (const int*)  d_in[2];
    const float* W1    = (const float*)d_in[3];
    const float* b1    = (const float*)d_in[4];
    const float* W2    = (const float*)d_in[5];
    const float* b2    = (const float*)d_in[6];
    const float* gamma = (const float*)d_in[7];
    const float* beta  = (const float*)d_in[8];
    const float* epsg  = (const float*)d_in[9];
    const float* l1w   = (const float*)d_in[10];
    const float* l1b   = (const float*)d_in[11];
    const float* l2w   = (const float*)d_in[12];
    const float* l2b   = (const float*)d_in[13];
    float* out = (float*)d_out;

    const int N = in_sizes[0] / HIDDEN;
    const int E = in_sizes[1] / 2;
    const int M = N + 1;

    float *agg, *zA, *zB, *pool, *cnt, *stats, *aff;
    int *deg, *rowptr, *cursor, *csr, *bsum;
    cudaGetSymbolAddress((void**)&agg,    g_agg);
    cudaGetSymbolAddress((void**)&zA,     g_zA);
    cudaGetSymbolAddress((void**)&zB,     g_zB);
    cudaGetSymbolAddress((void**)&pool,   g_pool);
    cudaGetSymbolAddress((void**)&cnt,    g_cnt);
    cudaGetSymbolAddress((void**)&stats,  g_stats);
    cudaGetSymbolAddress((void**)&aff,    g_aff);
    cudaGetSymbolAddress((void**)&deg,    g_deg);
    cudaGetSymbolAddress((void**)&rowptr, g_rowptr);
    cudaGetSymbolAddress((void**)&cursor, g_cursor);
    cudaGetSymbolAddress((void**)&csr,    g_csr);
    cudaGetSymbolAddress((void**)&bsum,   g_bsum);

    cudaFuncSetAttribute(gin_mlp_kernel,
                         cudaFuncAttributeMaxDynamicSharedMemorySize, SMEM_FUSED);

    cudaMemsetAsync(pool,  0, (size_t)NGRAPH * LAYERS * HIDDEN * sizeof(float), 0);
    cudaMemsetAsync(cnt,   0, (size_t)NGRAPH * sizeof(float), 0);
    cudaMemsetAsync(stats, 0, (size_t)LAYERS * 2 * HIDDEN * sizeof(float), 0);
    count_kernel<<<(N + 255) / 256, 256>>>(batch, cnt, N);

    // ---- CSR build (once) ----
    const int nb = (M + 1023) / 1024;
    cudaMemsetAsync(deg, 0, (size_t)M * sizeof(int), 0);
    deg_kernel<<<(E + 255) / 256, 256>>>(ei, deg, E);
    scan1_kernel<<<nb, 1024>>>(deg, rowptr, bsum, M);
    scan2_kernel<<<1, 256>>>(bsum, nb);
    scan3_kernel<<<nb, 1024>>>(rowptr, bsum, M);
    cudaMemcpyAsync(cursor, rowptr, (size_t)N * sizeof(int), cudaMemcpyDeviceToDevice, 0);
    fill_kernel<<<(E + 255) / 256, 256>>>(ei, cursor, csr, E);

    const int gemm_grid = (N + 127) / 128;
    const int agg_grid  = (N * 32 + 255) / 256;

    const float* zin = x;
    float* zouts[LAYERS] = {zA, zB, zA};

    for (int l = 0; l < LAYERS; l++) {
        agg_csr_kernel<<<agg_grid, 256>>>(zin, rowptr, csr, agg, N);

        const float* aff_prev = (l == 0) ? nullptr : (aff + (size_t)(l - 1) * 2 * HIDDEN);
        gin_mlp_kernel<<<gemm_grid, 256, SMEM_FUSED>>>(
            zin, agg, epsg + l, deg, aff_prev,
            W1 + (size_t)l * HIDDEN * HIDDEN, b1 + (size_t)l * HIDDEN,
            W2 + (size_t)l * HIDDEN * HIDDEN, b2 + (size_t)l * HIDDEN,
            zouts[l], N,
            stats + (size_t)l * 2 * HIDDEN, pool, batch, l * HIDDEN);

        affine_kernel<<<1, HIDDEN>>>(stats + (size_t)l * 2 * HIDDEN,
                                     gamma + (size_t)l * HIDDEN,
                                     beta  + (size_t)l * HIDDEN,
                                     aff + (size_t)l * 2 * HIDDEN, N);
        zin = zouts[l];
    }

    head_kernel<<<NGRAPH, HIDDEN>>>(pool, cnt, aff, l1w, l1b, l2w, l2b, out);
}